// round 1
// baseline (speedup 1.0000x reference)
#include <cuda_runtime.h>
#include <cstdint>

#define NUM_ITEMS 6714
#define RANK 100
#define NTHREADS 256
#define CAND_CAP 1024

__device__ __forceinline__ uint32_t flip_f32(uint32_t s) {
    // monotonic float -> uint mapping (larger float => larger uint)
    return s ^ ((s & 0x80000000u) ? 0xFFFFFFFFu : 0x80000000u);
}
__device__ __forceinline__ float unflip_f32(uint32_t k) {
    uint32_t s = (k & 0x80000000u) ? (k ^ 0x80000000u) : ~k;
    return __uint_as_float(s);
}

__global__ __launch_bounds__(NTHREADS) void logit_selector_kernel(
    const float* __restrict__ output,
    const int* __restrict__ labels,
    float* __restrict__ out_vals,    // [batch, RANK]
    float* __restrict__ out_labels)  // [batch]
{
    __shared__ uint32_t s_keys[NUM_ITEMS];
    __shared__ uint64_t s_cand[CAND_CAP];
    __shared__ uint32_t s_hist[256];
    __shared__ uint32_t s_prefix;
    __shared__ uint32_t s_k;
    __shared__ uint32_t s_cnt;
    __shared__ int s_found;   // position in target (reversed) order, -1 if absent

    const int row = blockIdx.x;
    const int tid = threadIdx.x;
    const float* row_ptr = output + (size_t)row * NUM_ITEMS;

    // ---- 1. stream row into smem as flipped keys (float2 vectorized; 6714 is even) ----
    const float2* row2 = reinterpret_cast<const float2*>(row_ptr);
    #pragma unroll 4
    for (int i = tid; i < NUM_ITEMS / 2; i += NTHREADS) {
        float2 v = row2[i];
        s_keys[2 * i]     = flip_f32(__float_as_uint(v.x));
        s_keys[2 * i + 1] = flip_f32(__float_as_uint(v.y));
    }
    if (tid == 0) { s_prefix = 0u; s_k = RANK; s_cnt = 0u; s_found = -1; }
    __syncthreads();

    // ---- 2. radix select: exact key of the 100th largest (4 x 8-bit passes) ----
    for (int pass = 0; pass < 4; ++pass) {
        const int shift = 24 - 8 * pass;
        const uint32_t hi_mask = (pass == 0) ? 0u : (0xFFFFFFFFu << (shift + 8));
        const uint32_t prefix = s_prefix;

        s_hist[tid] = 0u;  // NTHREADS == 256 bins
        __syncthreads();

        for (int i = tid; i < NUM_ITEMS; i += NTHREADS) {
            uint32_t key = s_keys[i];
            if ((key & hi_mask) == prefix)
                atomicAdd(&s_hist[(key >> shift) & 0xFFu], 1u);
        }
        __syncthreads();

        if (tid == 0) {
            uint32_t k = s_k;
            uint32_t cum = 0;
            int b = 255;
            for (; b >= 0; --b) {
                uint32_t c = s_hist[b];
                if (cum + c >= k) { s_k = k - cum; break; }
                cum += c;
            }
            s_prefix = prefix | ((uint32_t)b << shift);
        }
        __syncthreads();
    }
    const uint32_t thresh = s_prefix;

    // ---- 3. gather all elements >= thresh as (~key, idx) u64 ----
    for (int i = tid; i < NUM_ITEMS; i += NTHREADS) {
        uint32_t key = s_keys[i];
        if (key >= thresh) {
            uint32_t pos = atomicAdd(&s_cnt, 1u);
            if (pos < CAND_CAP)
                s_cand[pos] = ((uint64_t)(~key) << 32) | (uint32_t)i;
        }
    }
    __syncthreads();
    const uint32_t cnt = s_cnt;
    for (int i = tid; i < CAND_CAP; i += NTHREADS)
        if (i >= (int)cnt) s_cand[i] = ~0ull;
    __syncthreads();

    // ---- 4. bitonic sort ascending: slot 0 = largest value (ties: lower idx first) ----
    for (int kk = 2; kk <= CAND_CAP; kk <<= 1) {
        for (int j = kk >> 1; j > 0; j >>= 1) {
            for (int i = tid; i < CAND_CAP; i += NTHREADS) {
                int ixj = i ^ j;
                if (ixj > i) {
                    bool up = ((i & kk) == 0);
                    uint64_t a = s_cand[i], b = s_cand[ixj];
                    if ((a > b) == up) { s_cand[i] = b; s_cand[ixj] = a; }
                }
            }
            __syncthreads();
        }
    }

    // ---- 5. locate label among top-100 (sorted-descending slot j -> target pos 99-j) ----
    const int label = labels[row];
    if (tid < RANK) {
        if ((uint32_t)(s_cand[tid] & 0xFFFFFFFFu) == (uint32_t)label)
            s_found = (RANK - 1) - tid;   // unique: at most one writer
    }
    __syncthreads();
    const int found = s_found;
    const float label_val = unflip_f32(s_keys[label]);

    // ---- 6. write new_output (reversed order) and new_labels ----
    float* out_row = out_vals + (size_t)row * RANK;
    if (tid < RANK) {
        int j = tid;                              // target position
        uint64_t e = s_cand[(RANK - 1) - j];      // sorted-descending slot
        uint32_t fk = ~(uint32_t)(e >> 32);
        float v = unflip_f32(fk);
        if (j == 0 && found < 0) v = label_val;   // substitute missing label at col 0
        out_row[j] = v;
    }
    if (tid == 0)
        out_labels[row] = (float)(found < 0 ? 0 : found);
}

extern "C" void kernel_launch(void* const* d_in, const int* in_sizes, int n_in,
                              void* d_out, int out_size) {
    const float* output = (const float*)d_in[0];
    const int*   labels = (const int*)d_in[1];
    const int batch = in_sizes[1];               // labels element count

    float* out_vals   = (float*)d_out;
    float* out_labels = out_vals + (size_t)batch * RANK;

    logit_selector_kernel<<<batch, NTHREADS>>>(output, labels, out_vals, out_labels);
}

// round 2
// speedup vs baseline: 3.0634x; 3.0634x over previous
#include <cuda_runtime.h>
#include <cstdint>

#define NUM_ITEMS 6714
#define N2 3357            // float2 count per row (6714/2)
#define RANK 100
#define NTHREADS 256
#define CAND_CAP 2048
#define FINAL_CAP 256

__device__ __forceinline__ uint32_t flip_f32(uint32_t s) {
    return s ^ ((s & 0x80000000u) ? 0xFFFFFFFFu : 0x80000000u);
}
__device__ __forceinline__ float unflip_f32(uint32_t k) {
    uint32_t s = (k & 0x80000000u) ? (k ^ 0x80000000u) : ~k;
    return __uint_as_float(s);
}

struct Shared {
    unsigned long long cand[CAND_CAP];   // ((u64)(~key) << 32) | idx  (ascending == key desc, idx asc)
    unsigned long long fin[FINAL_CAP];
    uint32_t hist[256];
    uint32_t wsum[8];
    uint32_t cnt0, cntF, prefix, k;
    int found;
    float labelval;
};

// Find highest bucket b with suffix_sum(b) >= s->k; update s->prefix, s->k.
// Entry: caller synced after filling s->hist. Exit: caller must sync.
__device__ __forceinline__ void block_select(Shared* s, int shift) {
    const int tid = threadIdx.x;
    const int lane = tid & 31, wid = tid >> 5;
    uint32_t k = s->k;                    // read before internal syncs
    uint32_t c = s->hist[255 - tid];      // reversed: scan == suffix sum
    uint32_t v = c;
    #pragma unroll
    for (int o = 1; o < 32; o <<= 1) {
        uint32_t u = __shfl_up_sync(0xFFFFFFFFu, v, o);
        if (lane >= o) v += u;
    }
    if (lane == 31) s->wsum[wid] = v;
    __syncthreads();
    if (tid < 8) {
        uint32_t w = s->wsum[tid];
        #pragma unroll
        for (int o = 1; o < 8; o <<= 1) {
            uint32_t u = __shfl_up_sync(0xFFu, w, o);
            if (tid >= o) w += u;
        }
        s->wsum[tid] = w;
    }
    __syncthreads();
    if (wid > 0) v += s->wsum[wid - 1];
    // v = suffix_sum(b), b = 255 - tid; v - c = suffix_sum(b+1)
    if (v >= k && (v - c) < k) {          // exactly one thread
        s->prefix |= ((uint32_t)(255 - tid)) << shift;
        s->k = k - (v - c);
    }
}

__global__ __launch_bounds__(NTHREADS, 4) void logit_selector_kernel(
    const float* __restrict__ output,
    const int* __restrict__ labels,
    float* __restrict__ out_vals,
    float* __restrict__ out_labels)
{
    __shared__ Shared s;

    const int row = blockIdx.x;
    const int tid = threadIdx.x;
    const float* row_ptr = output + (size_t)row * NUM_ITEMS;
    const float2* row2 = reinterpret_cast<const float2*>(row_ptr);
    const int label = labels[row];

    // ---- load row into registers as flipped keys (<=14 float2 per thread) ----
    uint32_t keys[28];
    #pragma unroll
    for (int j = 0; j < 14; ++j) {
        int i = tid + j * NTHREADS;
        if (i < N2) {
            float2 v = row2[i];
            keys[2 * j]     = flip_f32(__float_as_uint(v.x));
            keys[2 * j + 1] = flip_f32(__float_as_uint(v.y));
        } else {
            keys[2 * j] = 0u; keys[2 * j + 1] = 0u;
        }
    }
    if (tid == 0) {
        s.cnt0 = 0u; s.cntF = 0u; s.prefix = 0u; s.k = RANK; s.found = -1;
        s.labelval = row_ptr[label];
    }
    s.hist[tid] = 0u;
    __syncthreads();

    // ---- pass 0 histogram from registers ----
    #pragma unroll
    for (int j = 0; j < 14; ++j) {
        if (tid + j * NTHREADS < N2) {
            atomicAdd(&s.hist[keys[2 * j] >> 24], 1u);
            atomicAdd(&s.hist[keys[2 * j + 1] >> 24], 1u);
        }
    }
    __syncthreads();
    block_select(&s, 24);
    __syncthreads();
    const uint32_t b0 = s.prefix >> 24;

    // ---- compact: keep all keys with top byte >= b0 (count in [100, ~1050]) ----
    #pragma unroll
    for (int j = 0; j < 14; ++j) {
        int i = tid + j * NTHREADS;
        if (i < N2) {
            uint32_t ka = keys[2 * j], kb = keys[2 * j + 1];
            if ((ka >> 24) >= b0) {
                uint32_t pos = atomicAdd(&s.cnt0, 1u);
                if (pos < CAND_CAP)
                    s.cand[pos] = ((unsigned long long)(~ka) << 32) | (uint32_t)(2 * i);
            }
            if ((kb >> 24) >= b0) {
                uint32_t pos = atomicAdd(&s.cnt0, 1u);
                if (pos < CAND_CAP)
                    s.cand[pos] = ((unsigned long long)(~kb) << 32) | (uint32_t)(2 * i + 1);
            }
        }
    }
    __syncthreads();
    const uint32_t cnt0 = min(s.cnt0, (uint32_t)CAND_CAP);

    // ---- radix passes 1..3 over the small compacted set ----
    #pragma unroll
    for (int pass = 1; pass < 4; ++pass) {
        const int shift = 24 - 8 * pass;
        const uint32_t hi_mask = 0xFFFFFFFFu << (shift + 8);
        const uint32_t prefix = s.prefix;
        s.hist[tid] = 0u;
        __syncthreads();
        for (uint32_t i = tid; i < cnt0; i += NTHREADS) {
            uint32_t key = ~(uint32_t)(s.cand[i] >> 32);
            if ((key & hi_mask) == prefix)
                atomicAdd(&s.hist[(key >> shift) & 0xFFu], 1u);
        }
        __syncthreads();
        block_select(&s, shift);
        __syncthreads();
    }
    const uint32_t thresh = s.prefix;

    // ---- final gather: keys >= thresh (count ~100) ----
    for (uint32_t i = tid; i < cnt0; i += NTHREADS) {
        unsigned long long p = s.cand[i];
        uint32_t key = ~(uint32_t)(p >> 32);
        if (key >= thresh) {
            uint32_t pos = atomicAdd(&s.cntF, 1u);
            if (pos < FINAL_CAP) s.fin[pos] = p;
        }
    }
    __syncthreads();
    const uint32_t cntF = min(s.cntF, (uint32_t)FINAL_CAP);

    // ---- exact rank via O(n^2) over ~100 candidates (broadcast LDS) ----
    int myj = -1;
    float myv = 0.0f;
    if (tid < (int)cntF) {
        unsigned long long p = s.fin[tid];
        int r = 0;
        for (uint32_t i = 0; i < cntF; ++i)
            r += (s.fin[i] < p);
        if (r < RANK) {
            myj = (RANK - 1) - r;                       // target column
            myv = unflip_f32(~(uint32_t)(p >> 32));
            if ((uint32_t)(p & 0xFFFFFFFFu) == (uint32_t)label)
                s.found = myj;
        }
    }
    __syncthreads();
    const int found = s.found;

    float* out_row = out_vals + (size_t)row * RANK;
    if (myj >= 0) {
        float v = (myj == 0 && found < 0) ? s.labelval : myv;
        out_row[myj] = v;
    }
    if (tid == 0)
        out_labels[row] = (float)(found < 0 ? 0 : found);
}

extern "C" void kernel_launch(void* const* d_in, const int* in_sizes, int n_in,
                              void* d_out, int out_size) {
    const float* output = (const float*)d_in[0];
    const int*   labels = (const int*)d_in[1];
    const int batch = in_sizes[1];

    float* out_vals   = (float*)d_out;
    float* out_labels = out_vals + (size_t)batch * RANK;

    logit_selector_kernel<<<batch, NTHREADS>>>(output, labels, out_vals, out_labels);
}

// round 4
// speedup vs baseline: 3.8453x; 1.2553x over previous
#include <cuda_runtime.h>
#include <cstdint>

#define NUM_ITEMS 6714
#define N2 3357            // float2 per row
#define RANK 100
#define NTHREADS 256
#define KPT 14             // float2 per thread
#define CAND_CAP 2048
#define STOP1 1920
#define STOP2 200
#define FINAL_CAP 320
#define MAXITER 40

__device__ __forceinline__ uint32_t flip_f32(uint32_t s) {
    return s ^ ((s & 0x80000000u) ? 0xFFFFFFFFu : 0x80000000u);
}
__device__ __forceinline__ float unflip_f32(uint32_t k) {
    uint32_t s = (k & 0x80000000u) ? (k ^ 0x80000000u) : ~k;
    return __uint_as_float(s);
}

struct Shared {
    unsigned long long cand[CAND_CAP];  // ((u64)(~key)<<32)|idx : ascending == (key desc, idx asc)
    unsigned long long fin[FINAL_CAP];
    uint32_t wred[MAXITER][8];          // per-warp partial counts, one slot per bit-iteration
    uint32_t cnt0, cntF;
    int found;
    float labelval;
};

__global__ __launch_bounds__(NTHREADS, 4) void logit_selector_kernel(
    const float* __restrict__ output,
    const int* __restrict__ labels,
    float* __restrict__ out_vals,
    float* __restrict__ out_labels)
{
    __shared__ Shared s;

    const int row  = blockIdx.x;
    const int tid  = threadIdx.x;
    const int lane = tid & 31;
    const int wid  = tid >> 5;
    const float* row_ptr = output + (size_t)row * NUM_ITEMS;
    const float2* row2 = reinterpret_cast<const float2*>(row_ptr);
    const int label = labels[row];

    // ---- load row into registers as flipped keys ----
    uint32_t keys[2 * KPT];
    #pragma unroll
    for (int j = 0; j < KPT; ++j) {
        int i = tid + j * NTHREADS;
        if (i < N2) {
            float2 v = row2[i];
            keys[2 * j]     = flip_f32(__float_as_uint(v.x));
            keys[2 * j + 1] = flip_f32(__float_as_uint(v.y));
        } else {
            keys[2 * j] = 0u; keys[2 * j + 1] = 0u;
        }
    }
    if (tid == 0) {
        s.cnt0 = 0u; s.cntF = 0u; s.found = -1;
        s.labelval = row_ptr[label];
    }
    __syncthreads();

    // ---- phase 1: bitwise top-k narrowing over register keys (ballot counting) ----
    // invariant: candidates = keys with (key >> (sh+1)) == pfx; k = rank of target
    // among candidates (1-based from top); cand = candidate count.
    uint32_t pfx = 0u, k = RANK, cand = NUM_ITEMS;
    int sh = 31, iter = 0;
    while (cand > STOP1 && sh >= 0) {
        const uint32_t t = (pfx << 1) | 1u;
        int c = 0;
        #pragma unroll
        for (int j = 0; j < 2 * KPT; ++j)
            c += ((keys[j] >> sh) == t);      // padded zeros never match (t >= 1)
        c = __reduce_add_sync(0xFFFFFFFFu, c);
        if (lane == 0) s.wred[iter][wid] = (uint32_t)c;
        __syncthreads();
        uint32_t cnt1 = 0;
        #pragma unroll
        for (int w = 0; w < 8; ++w) cnt1 += s.wred[iter][w];
        if (cnt1 >= k) { pfx = t; cand = cnt1; }
        else           { k -= cnt1; pfx <<= 1; cand -= cnt1; }
        --sh; ++iter;
    }
    const uint32_t thresh1 = pfx << (sh + 1);

    // ---- compact: keys >= thresh1 into smem (count = (100-k) + cand <= 100+STOP1) ----
    // Fixed 28 iterations for every thread -> ballot always sees full warps.
    #pragma unroll
    for (int j = 0; j < 2 * KPT; ++j) {
        int half = j & 1;
        int i2 = tid + (j >> 1) * NTHREADS;         // float2 index
        int idx = 2 * i2 + half;
        uint32_t key = keys[j];
        bool p = (i2 < N2) && (key >= thresh1);
        uint32_t m = __ballot_sync(0xFFFFFFFFu, p);
        if (m) {
            int leader = __ffs(m) - 1;
            uint32_t base = 0;
            if (lane == leader) base = atomicAdd(&s.cnt0, (uint32_t)__popc(m));
            base = __shfl_sync(0xFFFFFFFFu, base, leader);
            if (p) {
                uint32_t pos = base + (uint32_t)__popc(m & ((1u << lane) - 1u));
                if (pos < CAND_CAP)
                    s.cand[pos] = ((unsigned long long)(~key) << 32) | (uint32_t)idx;
            }
        }
    }
    __syncthreads();
    const uint32_t cnt0 = min(s.cnt0, (uint32_t)CAND_CAP);
    // Uniform (multiple-of-NTHREADS) upper bound for warp-collective loops below.
    const uint32_t cnt0_pad = (cnt0 + NTHREADS - 1) / NTHREADS * NTHREADS;

    // ---- phase 2: continue bit-search over the compacted smem set ----
    const uint32_t* ch = reinterpret_cast<const uint32_t*>(s.cand);  // hi word at 2*i+1
    while (cand > STOP2 && sh >= 0) {
        const uint32_t t = (pfx << 1) | 1u;
        int c = 0;
        for (uint32_t i = tid; i < cnt0; i += NTHREADS) {
            uint32_t key = ~ch[2 * i + 1];
            c += ((key >> sh) == t);
        }
        c = __reduce_add_sync(0xFFFFFFFFu, c);    // after loop exit: warp reconverged, safe
        if (lane == 0) s.wred[iter][wid] = (uint32_t)c;
        __syncthreads();
        uint32_t cnt1 = 0;
        #pragma unroll
        for (int w = 0; w < 8; ++w) cnt1 += s.wred[iter][w];
        if (cnt1 >= k) { pfx = t; cand = cnt1; }
        else           { k -= cnt1; pfx <<= 1; cand -= cnt1; }
        --sh; ++iter;
    }
    const uint32_t thresh2 = pfx << (sh + 1);

    // ---- final gather: keys >= thresh2 (count <= 100 + STOP2 <= FINAL_CAP) ----
    // Padded bound: every lane runs the same trip count; bounds check folded into p.
    for (uint32_t i = tid; i < cnt0_pad; i += NTHREADS) {
        unsigned long long p64 = 0ull;
        bool p = false;
        if (i < cnt0) {
            p64 = s.cand[i];
            p = (~(uint32_t)(p64 >> 32)) >= thresh2;
        }
        uint32_t m = __ballot_sync(0xFFFFFFFFu, p);
        if (m) {
            int leader = __ffs(m) - 1;
            uint32_t base = 0;
            if (lane == leader) base = atomicAdd(&s.cntF, (uint32_t)__popc(m));
            base = __shfl_sync(0xFFFFFFFFu, base, leader);
            if (p) {
                uint32_t pos = base + (uint32_t)__popc(m & ((1u << lane) - 1u));
                if (pos < FINAL_CAP) s.fin[pos] = p64;
            }
        }
    }
    __syncthreads();
    const uint32_t cntF = min(s.cntF, (uint32_t)FINAL_CAP);

    // ---- exact rank via O(n^2) over ~100-300 candidates (broadcast LDS) ----
    int myj = -1;
    float myv = 0.0f;
    if (tid < (int)cntF) {
        unsigned long long p64 = s.fin[tid];
        int r = 0;
        for (uint32_t i = 0; i < cntF; ++i)
            r += (s.fin[i] < p64);
        if (r < RANK) {
            myj = (RANK - 1) - r;
            myv = unflip_f32(~(uint32_t)(p64 >> 32));
            if ((uint32_t)(p64 & 0xFFFFFFFFu) == (uint32_t)label)
                s.found = myj;
        }
    }
    __syncthreads();
    const int found = s.found;

    float* out_row = out_vals + (size_t)row * RANK;
    if (myj >= 0) {
        float v = (myj == 0 && found < 0) ? s.labelval : myv;
        out_row[myj] = v;
    }
    if (tid == 0)
        out_labels[row] = (float)(found < 0 ? 0 : found);
}

extern "C" void kernel_launch(void* const* d_in, const int* in_sizes, int n_in,
                              void* d_out, int out_size) {
    const float* output = (const float*)d_in[0];
    const int*   labels = (const int*)d_in[1];
    const int batch = in_sizes[1];

    float* out_vals   = (float*)d_out;
    float* out_labels = out_vals + (size_t)batch * RANK;

    logit_selector_kernel<<<batch, NTHREADS>>>(output, labels, out_vals, out_labels);
}